// round 7
// baseline (speedup 1.0000x reference)
#include <cuda_runtime.h>
#include <cuda_fp16.h>
#include <cstdint>
#include <math.h>

#define NROWS 4096
#define DIM   1024
#define TEMP_INV 20.0f
#define EPS 1e-8f

#define BM 128
#define BN 128
#define BK 32
#define NKT (DIM / BK)        // 32 k-tiles
#define ROWB 64               // smem row stride in bytes (XOR swizzle)
#define MAT_BYTES (128 * ROWB)        // 8192 per matrix per stage
#define OFF_A 0
#define OFF_B MAT_BYTES
#define STAGE  (2 * MAT_BYTES)        // 16384
#define NSTG   4
#define SMEM_TOTAL (NSTG * STAGE)     // 65536 -> 2 CTAs/SM

// swizzled byte offset within one matrix tile: row r (0..127), chunk c (0..3)
#define SWZ_OFF(r, c) ((r) * ROWB + (((c) ^ (((r) >> 1) & 3)) << 4))

// fp16 normalized inputs (allocation-free scratch)
__device__ __half g_xh[NROWS * DIM];
__device__ __half g_yh[NROWS * DIM];

// ---------------------------------------------------------------------------
// helpers
// ---------------------------------------------------------------------------
__device__ __forceinline__ uint32_t smem_to_u32(const void* p) {
    uint32_t a;
    asm("{ .reg .u64 t; cvta.to.shared.u64 t, %1; cvt.u32.u64 %0, t; }"
        : "=r"(a) : "l"(p));
    return a;
}

__device__ __forceinline__ void cp_async16(uint32_t s, const void* g) {
    asm volatile("cp.async.cg.shared.global [%0], [%1], 16;" :: "r"(s), "l"(g));
}

__device__ __forceinline__ void ldsm_x4(uint32_t& r0, uint32_t& r1,
                                        uint32_t& r2, uint32_t& r3, uint32_t addr) {
    asm volatile("ldmatrix.sync.aligned.m8n8.x4.shared.b16 {%0,%1,%2,%3}, [%4];"
                 : "=r"(r0), "=r"(r1), "=r"(r2), "=r"(r3) : "r"(addr));
}

__device__ __forceinline__ void mma16816(float* d, const uint32_t* a,
                                         uint32_t b0, uint32_t b1) {
    asm volatile(
        "mma.sync.aligned.m16n8k16.row.col.f32.f16.f16.f32 "
        "{%0,%1,%2,%3}, {%4,%5,%6,%7}, {%8,%9}, {%0,%1,%2,%3};"
        : "+f"(d[0]), "+f"(d[1]), "+f"(d[2]), "+f"(d[3])
        : "r"(a[0]), "r"(a[1]), "r"(a[2]), "r"(a[3]), "r"(b0), "r"(b1));
}

// ---------------------------------------------------------------------------
// Kernel 1: normalize rows, emit fp16.
// ---------------------------------------------------------------------------
__global__ __launch_bounds__(256) void normalize_kernel(
    const float* __restrict__ x, const float* __restrict__ y) {
    int row = blockIdx.x;
    const float* src;
    __half* dst;
    if (row < NROWS) {
        src = x + (size_t)row * DIM;
        dst = g_xh + (size_t)row * DIM;
    } else {
        src = y + (size_t)(row - NROWS) * DIM;
        dst = g_yh + (size_t)(row - NROWS) * DIM;
    }
    int tid = threadIdx.x;
    float4 v = ((const float4*)src)[tid];
    float s = v.x * v.x + v.y * v.y + v.z * v.z + v.w * v.w;

    __shared__ float red[8];
    #pragma unroll
    for (int o = 16; o; o >>= 1) s += __shfl_down_sync(0xffffffffu, s, o);
    if ((tid & 31) == 0) red[tid >> 5] = s;
    __syncthreads();
    if (tid < 8) {
        float t = red[tid];
        #pragma unroll
        for (int o = 4; o; o >>= 1) t += __shfl_down_sync(0xffu, t, o);
        if (tid == 0) red[0] = t;
    }
    __syncthreads();
    float inv = 1.0f / fmaxf(sqrtf(red[0]), EPS);

    __half2 p0 = __floats2half2_rn(v.x * inv, v.y * inv);
    __half2 p1 = __floats2half2_rn(v.z * inv, v.w * inv);
    ((uint2*)dst)[tid] = make_uint2(*(uint32_t*)&p0, *(uint32_t*)&p1);
}

// ---------------------------------------------------------------------------
// Kernel 2: fp16 HMMA GEMM. C[n][m] = 20 * (xn[n] . yn[m])
// 128x128 CTA tile, BK=32, 4-stage cp.async pipeline, 4 warps (2x2),
// warp tile 64x64, 2 CTAs/SM, mma.m16n8k16.f16, fp32 accum.
// ---------------------------------------------------------------------------
__global__ __launch_bounds__(128, 2) void gemm_hmma(float* __restrict__ C) {
    extern __shared__ __align__(128) char smem[];
    const int tid = threadIdx.x;
    const int lane = tid & 31;
    const int wid = tid >> 5;
    const int wm = wid >> 1;       // 0..1  (M)
    const int wn = wid & 1;        // 0..1  (N)
    const int bx = blockIdx.x;     // N tile
    const int by = blockIdx.y;     // M tile

    const uint32_t sbase = smem_to_u32(smem);

    const __half* __restrict__ A = g_xh + (size_t)(by * BM) * DIM;
    const __half* __restrict__ B = g_yh + (size_t)(bx * BN) * DIM;

    // per-thread load mapping: 512 16B-chunks per matrix, 4 per thread
    auto load_stage = [&](int sidx, int kt) {
        const uint32_t sb = sbase + sidx * STAGE;
        const int k0 = kt * BK;
        #pragma unroll
        for (int i = 0; i < 4; i++) {
            int idx = tid + i * 128;
            int row = idx >> 2;
            int ch  = idx & 3;
            uint32_t so = SWZ_OFF(row, ch);
            size_t go = (size_t)row * DIM + k0 + ch * 8;
            cp_async16(sb + OFF_A + so, A + go);
            cp_async16(sb + OFF_B + so, B + go);
        }
        asm volatile("cp.async.commit_group;" ::: "memory");
    };

    float acc[4][8][4];
    #pragma unroll
    for (int i = 0; i < 4; i++)
        #pragma unroll
        for (int j = 0; j < 8; j++)
            #pragma unroll
            for (int k = 0; k < 4; k++) acc[i][j][k] = 0.0f;

    load_stage(0, 0);
    load_stage(1, 1);
    load_stage(2, 2);

    // ldmatrix row/chunk mapping
    const int arow = wm * 64 + (lane & 15);   // + mi*16
    const int brow = wn * 64 + (lane & 15);   // + nj*16
    const int chi  = lane >> 4;               // 0 or 1

    for (int kt = 0; kt < NKT; kt++) {
        if (kt + 2 < NKT)
            asm volatile("cp.async.wait_group 2;" ::: "memory");
        else if (kt + 1 < NKT)
            asm volatile("cp.async.wait_group 1;" ::: "memory");
        else
            asm volatile("cp.async.wait_group 0;" ::: "memory");
        __syncthreads();

        // refill the buffer consumed at kt-1 (sync above makes it safe)
        if (kt + 3 < NKT) load_stage((kt + 3) % NSTG, kt + 3);

        const uint32_t sb = sbase + (kt % NSTG) * STAGE;
        const uint32_t sA = sb + OFF_A;
        const uint32_t sB = sb + OFF_B;

        #pragma unroll
        for (int ks = 0; ks < 2; ks++) {
            const int ch = ks * 2 + chi;     // chunk index 0..3

            uint32_t a[4][4];
            #pragma unroll
            for (int mi = 0; mi < 4; mi++) {
                uint32_t ro = SWZ_OFF(arow + mi * 16, ch);
                ldsm_x4(a[mi][0], a[mi][1], a[mi][2], a[mi][3], sA + ro);
            }
            uint32_t b[4][4];
            #pragma unroll
            for (int nj = 0; nj < 4; nj++) {
                uint32_t ro = SWZ_OFF(brow + nj * 16, ch);
                ldsm_x4(b[nj][0], b[nj][1], b[nj][2], b[nj][3], sB + ro);
            }

            #pragma unroll
            for (int mi = 0; mi < 4; mi++) {
                #pragma unroll
                for (int nt = 0; nt < 8; nt++) {
                    const int nj = nt >> 1, h = nt & 1;
                    mma16816(acc[mi][nt], a[mi], b[nj][h], b[nj][h + 2]);
                }
            }
        }
    }

    // epilogue: scale by 20, direct float2 stores
    const int erow = by * BM + wm * 64 + (lane >> 2);
    const int ecol = bx * BN + wn * 64 + (lane & 3) * 2;
    #pragma unroll
    for (int mi = 0; mi < 4; mi++) {
        #pragma unroll
        for (int nt = 0; nt < 8; nt++) {
            float* p0 = C + (size_t)(erow + mi * 16) * NROWS + ecol + nt * 8;
            float* p1 = p0 + 8 * NROWS;
            *(float2*)p0 = make_float2(acc[mi][nt][0] * TEMP_INV,
                                       acc[mi][nt][1] * TEMP_INV);
            *(float2*)p1 = make_float2(acc[mi][nt][2] * TEMP_INV,
                                       acc[mi][nt][3] * TEMP_INV);
        }
    }
}

extern "C" void kernel_launch(void* const* d_in, const int* in_sizes, int n_in,
                              void* d_out, int out_size) {
    const float* x = (const float*)d_in[0];
    const float* y = (const float*)d_in[1];
    float* out = (float*)d_out;

    normalize_kernel<<<2 * NROWS, 256>>>(x, y);

    cudaFuncSetAttribute(gemm_hmma,
                         cudaFuncAttributeMaxDynamicSharedMemorySize, SMEM_TOTAL);
    dim3 grid(NROWS / BN, NROWS / BM);
    gemm_hmma<<<grid, 128, SMEM_TOTAL>>>(out);
}

// round 8
// speedup vs baseline: 1.0934x; 1.0934x over previous
#include <cuda_runtime.h>
#include <cuda_fp16.h>
#include <cstdint>
#include <math.h>

#define NROWS 4096
#define DIM   1024
#define TEMP_INV 20.0f
#define EPS 1e-8f

#define BM 128
#define BN 128
#define BK 64
#define NKT (DIM / BK)        // 16 k-tiles
#define ROWB 128              // smem row stride in bytes (XOR swizzle, 8 chunks)
#define MAT_BYTES (128 * ROWB)        // 16384 per matrix per stage
#define OFF_A 0
#define OFF_B MAT_BYTES
#define STAGE  (2 * MAT_BYTES)        // 32768
#define NSTG   3
#define SMEM_TOTAL (NSTG * STAGE)     // 98304 -> 2 CTAs/SM

// swizzled byte offset: row r (0..127), 16B chunk c (0..7)
// conflict-free: per ldmatrix phase rows 0..7 hit 8 distinct 16B slots
#define SWZ_OFF(r, c) ((r) * ROWB + ((((c) ^ ((r) & 7))) << 4))

// fp16 normalized inputs (allocation-free scratch)
__device__ __half g_xh[NROWS * DIM];
__device__ __half g_yh[NROWS * DIM];

// ---------------------------------------------------------------------------
// helpers
// ---------------------------------------------------------------------------
__device__ __forceinline__ uint32_t smem_to_u32(const void* p) {
    uint32_t a;
    asm("{ .reg .u64 t; cvta.to.shared.u64 t, %1; cvt.u32.u64 %0, t; }"
        : "=r"(a) : "l"(p));
    return a;
}

__device__ __forceinline__ void cp_async16(uint32_t s, const void* g) {
    asm volatile("cp.async.cg.shared.global [%0], [%1], 16;" :: "r"(s), "l"(g));
}

__device__ __forceinline__ void ldsm_x4(uint32_t& r0, uint32_t& r1,
                                        uint32_t& r2, uint32_t& r3, uint32_t addr) {
    asm volatile("ldmatrix.sync.aligned.m8n8.x4.shared.b16 {%0,%1,%2,%3}, [%4];"
                 : "=r"(r0), "=r"(r1), "=r"(r2), "=r"(r3) : "r"(addr));
}

__device__ __forceinline__ void mma16816(float* d, const uint32_t* a,
                                         uint32_t b0, uint32_t b1) {
    asm volatile(
        "mma.sync.aligned.m16n8k16.row.col.f32.f16.f16.f32 "
        "{%0,%1,%2,%3}, {%4,%5,%6,%7}, {%8,%9}, {%0,%1,%2,%3};"
        : "+f"(d[0]), "+f"(d[1]), "+f"(d[2]), "+f"(d[3])
        : "r"(a[0]), "r"(a[1]), "r"(a[2]), "r"(a[3]), "r"(b0), "r"(b1));
}

// ---------------------------------------------------------------------------
// Kernel 1: normalize rows, emit fp16.
// ---------------------------------------------------------------------------
__global__ __launch_bounds__(256) void normalize_kernel(
    const float* __restrict__ x, const float* __restrict__ y) {
    int row = blockIdx.x;
    const float* src;
    __half* dst;
    if (row < NROWS) {
        src = x + (size_t)row * DIM;
        dst = g_xh + (size_t)row * DIM;
    } else {
        src = y + (size_t)(row - NROWS) * DIM;
        dst = g_yh + (size_t)(row - NROWS) * DIM;
    }
    int tid = threadIdx.x;
    float4 v = ((const float4*)src)[tid];
    float s = v.x * v.x + v.y * v.y + v.z * v.z + v.w * v.w;

    __shared__ float red[8];
    #pragma unroll
    for (int o = 16; o; o >>= 1) s += __shfl_down_sync(0xffffffffu, s, o);
    if ((tid & 31) == 0) red[tid >> 5] = s;
    __syncthreads();
    if (tid < 8) {
        float t = red[tid];
        #pragma unroll
        for (int o = 4; o; o >>= 1) t += __shfl_down_sync(0xffu, t, o);
        if (tid == 0) red[0] = t;
    }
    __syncthreads();
    float inv = 1.0f / fmaxf(sqrtf(red[0]), EPS);

    __half2 p0 = __floats2half2_rn(v.x * inv, v.y * inv);
    __half2 p1 = __floats2half2_rn(v.z * inv, v.w * inv);
    ((uint2*)dst)[tid] = make_uint2(*(uint32_t*)&p0, *(uint32_t*)&p1);
}

// ---------------------------------------------------------------------------
// Kernel 2: fp16 HMMA GEMM. C[n][m] = 20 * (xn[n] . yn[m])
// 128x128 CTA tile, BK=64, 3-stage cp.async pipeline, 4 warps (2x2),
// warp tile 64x64, register double-buffered fragments, 2 CTAs/SM.
// ---------------------------------------------------------------------------
__global__ __launch_bounds__(128, 2) void gemm_hmma(float* __restrict__ C) {
    extern __shared__ __align__(128) char smem[];
    const int tid = threadIdx.x;
    const int lane = tid & 31;
    const int wid = tid >> 5;
    const int wm = wid >> 1;       // 0..1  (M)
    const int wn = wid & 1;        // 0..1  (N)
    const int bx = blockIdx.x;     // N tile
    const int by = blockIdx.y;     // M tile

    const uint32_t sbase = smem_to_u32(smem);

    const __half* __restrict__ A = g_xh + (size_t)(by * BM) * DIM;
    const __half* __restrict__ B = g_yh + (size_t)(bx * BN) * DIM;

    // loader: 128 rows x 8 chunks per matrix = 1024 chunks; 8 per thread/matrix
    auto load_stage = [&](int sidx, int kt) {
        const uint32_t sb = sbase + sidx * STAGE;
        const int k0 = kt * BK;
        #pragma unroll
        for (int i = 0; i < 8; i++) {
            int idx = tid + i * 128;
            int row = idx >> 3;
            int ch  = idx & 7;
            uint32_t so = SWZ_OFF(row, ch);
            size_t go = (size_t)row * DIM + k0 + ch * 8;
            cp_async16(sb + OFF_A + so, A + go);
            cp_async16(sb + OFF_B + so, B + go);
        }
        asm volatile("cp.async.commit_group;" ::: "memory");
    };

    float acc[4][8][4];
    #pragma unroll
    for (int i = 0; i < 4; i++)
        #pragma unroll
        for (int j = 0; j < 8; j++)
            #pragma unroll
            for (int k = 0; k < 4; k++) acc[i][j][k] = 0.0f;

    load_stage(0, 0);
    load_stage(1, 1);

    // ldmatrix row/chunk mapping
    const int arow = wm * 64 + (lane & 15);   // + mi*16
    const int brow = wn * 64 + (lane & 15);   // + nj*16
    const int chi  = lane >> 4;               // 0 or 1 (16B half of 32B k-slice)

    uint32_t a[2][4][4], b[2][4][4];

    for (int kt = 0; kt < NKT; kt++) {
        if (kt + 1 < NKT)
            asm volatile("cp.async.wait_group 1;" ::: "memory");
        else
            asm volatile("cp.async.wait_group 0;" ::: "memory");
        __syncthreads();

        if (kt + 2 < NKT) load_stage((kt + 2) % NSTG, kt + 2);

        const uint32_t sb = sbase + (kt % NSTG) * STAGE;
        const uint32_t sA = sb + OFF_A;
        const uint32_t sB = sb + OFF_B;

        // fragment loader for one 16-col k-slice (ks = 0..3)
        auto ld_frags = [&](int ks, uint32_t af[4][4], uint32_t bf[4][4]) {
            const int ch = ks * 2 + chi;
            #pragma unroll
            for (int mi = 0; mi < 4; mi++) {
                uint32_t ro = SWZ_OFF(arow + mi * 16, ch);
                ldsm_x4(af[mi][0], af[mi][1], af[mi][2], af[mi][3], sA + ro);
            }
            #pragma unroll
            for (int nj = 0; nj < 4; nj++) {
                uint32_t ro = SWZ_OFF(brow + nj * 16, ch);
                ldsm_x4(bf[nj][0], bf[nj][1], bf[nj][2], bf[nj][3], sB + ro);
            }
        };

        ld_frags(0, a[0], b[0]);

        #pragma unroll
        for (int ks = 0; ks < 4; ks++) {
            const int cur = ks & 1;
            const int nxt = cur ^ 1;
            if (ks < 3) ld_frags(ks + 1, a[nxt], b[nxt]);

            #pragma unroll
            for (int mi = 0; mi < 4; mi++) {
                #pragma unroll
                for (int nt = 0; nt < 8; nt++) {
                    const int nj = nt >> 1, h = nt & 1;
                    mma16816(acc[mi][nt], a[cur][mi], b[cur][nj][h], b[cur][nj][h + 2]);
                }
            }
        }
    }

    // epilogue: scale by 20, direct float2 stores
    const int erow = by * BM + wm * 64 + (lane >> 2);
    const int ecol = bx * BN + wn * 64 + (lane & 3) * 2;
    #pragma unroll
    for (int mi = 0; mi < 4; mi++) {
        #pragma unroll
        for (int nt = 0; nt < 8; nt++) {
            float* p0 = C + (size_t)(erow + mi * 16) * NROWS + ecol + nt * 8;
            float* p1 = p0 + 8 * NROWS;
            *(float2*)p0 = make_float2(acc[mi][nt][0] * TEMP_INV,
                                       acc[mi][nt][1] * TEMP_INV);
            *(float2*)p1 = make_float2(acc[mi][nt][2] * TEMP_INV,
                                       acc[mi][nt][3] * TEMP_INV);
        }
    }
}

extern "C" void kernel_launch(void* const* d_in, const int* in_sizes, int n_in,
                              void* d_out, int out_size) {
    const float* x = (const float*)d_in[0];
    const float* y = (const float*)d_in[1];
    float* out = (float*)d_out;

    normalize_kernel<<<2 * NROWS, 256>>>(x, y);

    cudaFuncSetAttribute(gemm_hmma,
                         cudaFuncAttributeMaxDynamicSharedMemorySize, SMEM_TOTAL);
    dim3 grid(NROWS / BN, NROWS / BM);
    gemm_hmma<<<grid, 128, SMEM_TOTAL>>>(out);
}

// round 9
// speedup vs baseline: 1.0946x; 1.0011x over previous
#include <cuda_runtime.h>
#include <cuda_fp16.h>
#include <cstdint>
#include <math.h>

#define NROWS 4096
#define DIM   1024
#define TEMP_INV 20.0f
#define EPS 1e-8f

#define BM 128
#define BN 64
#define BK 64
#define NKT (DIM / BK)        // 16 k-tiles
#define ROWB 128              // smem row stride in bytes (XOR swizzle, 8 chunks)
#define A_BYTES (BM * ROWB)           // 16384
#define B_BYTES (BN * ROWB)           // 8192
#define OFF_A 0
#define OFF_B A_BYTES
#define STAGE  (A_BYTES + B_BYTES)    // 24576
#define NSTG   3
#define SMEM_TOTAL (NSTG * STAGE)     // 73728 -> 3 CTAs/SM

// swizzled byte offset: row r, 16B chunk c (0..7); conflict-free for
// 8-row ldmatrix phases and for the cp.async write pattern
#define SWZ_OFF(r, c) ((r) * ROWB + ((((c) ^ ((r) & 7))) << 4))

// fp16 normalized inputs (allocation-free scratch)
__device__ __half g_xh[NROWS * DIM];
__device__ __half g_yh[NROWS * DIM];

// ---------------------------------------------------------------------------
// helpers
// ---------------------------------------------------------------------------
__device__ __forceinline__ uint32_t smem_to_u32(const void* p) {
    uint32_t a;
    asm("{ .reg .u64 t; cvta.to.shared.u64 t, %1; cvt.u32.u64 %0, t; }"
        : "=r"(a) : "l"(p));
    return a;
}

__device__ __forceinline__ void cp_async16(uint32_t s, const void* g) {
    asm volatile("cp.async.cg.shared.global [%0], [%1], 16;" :: "r"(s), "l"(g));
}

__device__ __forceinline__ void ldsm_x4(uint32_t& r0, uint32_t& r1,
                                        uint32_t& r2, uint32_t& r3, uint32_t addr) {
    asm volatile("ldmatrix.sync.aligned.m8n8.x4.shared.b16 {%0,%1,%2,%3}, [%4];"
                 : "=r"(r0), "=r"(r1), "=r"(r2), "=r"(r3) : "r"(addr));
}

__device__ __forceinline__ void mma16816(float* d, const uint32_t* a,
                                         uint32_t b0, uint32_t b1) {
    asm volatile(
        "mma.sync.aligned.m16n8k16.row.col.f32.f16.f16.f32 "
        "{%0,%1,%2,%3}, {%4,%5,%6,%7}, {%8,%9}, {%0,%1,%2,%3};"
        : "+f"(d[0]), "+f"(d[1]), "+f"(d[2]), "+f"(d[3])
        : "r"(a[0]), "r"(a[1]), "r"(a[2]), "r"(a[3]), "r"(b0), "r"(b1));
}

// ---------------------------------------------------------------------------
// Kernel 1: normalize rows, emit fp16.
// ---------------------------------------------------------------------------
__global__ __launch_bounds__(256) void normalize_kernel(
    const float* __restrict__ x, const float* __restrict__ y) {
    int row = blockIdx.x;
    const float* src;
    __half* dst;
    if (row < NROWS) {
        src = x + (size_t)row * DIM;
        dst = g_xh + (size_t)row * DIM;
    } else {
        src = y + (size_t)(row - NROWS) * DIM;
        dst = g_yh + (size_t)(row - NROWS) * DIM;
    }
    int tid = threadIdx.x;
    float4 v = ((const float4*)src)[tid];
    float s = v.x * v.x + v.y * v.y + v.z * v.z + v.w * v.w;

    __shared__ float red[8];
    #pragma unroll
    for (int o = 16; o; o >>= 1) s += __shfl_down_sync(0xffffffffu, s, o);
    if ((tid & 31) == 0) red[tid >> 5] = s;
    __syncthreads();
    if (tid < 8) {
        float t = red[tid];
        #pragma unroll
        for (int o = 4; o; o >>= 1) t += __shfl_down_sync(0xffu, t, o);
        if (tid == 0) red[0] = t;
    }
    __syncthreads();
    float inv = 1.0f / fmaxf(sqrtf(red[0]), EPS);

    __half2 p0 = __floats2half2_rn(v.x * inv, v.y * inv);
    __half2 p1 = __floats2half2_rn(v.z * inv, v.w * inv);
    ((uint2*)dst)[tid] = make_uint2(*(uint32_t*)&p0, *(uint32_t*)&p1);
}

// ---------------------------------------------------------------------------
// Kernel 2: fp16 HMMA GEMM. C[n][m] = 20 * (xn[n] . yn[m])
// 128x64 CTA tile, BK=64, 3-stage cp.async pipeline, 4 warps (2x2),
// warp tile 64x32, register double-buffered fragments, 3 CTAs/SM.
// ---------------------------------------------------------------------------
__global__ __launch_bounds__(128, 3) void gemm_hmma(float* __restrict__ C) {
    extern __shared__ __align__(128) char smem[];
    const int tid = threadIdx.x;
    const int lane = tid & 31;
    const int wid = tid >> 5;
    const int wm = wid >> 1;       // 0..1  (M)
    const int wn = wid & 1;        // 0..1  (N)
    const int bx = blockIdx.x;     // N tile (0..63)
    const int by = blockIdx.y;     // M tile (0..31)

    const uint32_t sbase = smem_to_u32(smem);

    const __half* __restrict__ A = g_xh + (size_t)(by * BM) * DIM;
    const __half* __restrict__ B = g_yh + (size_t)(bx * BN) * DIM;

    // loader: A 128x8 chunks (8/thread), B 64x8 chunks (4/thread)
    auto load_stage = [&](int sidx, int kt) {
        const uint32_t sb = sbase + sidx * STAGE;
        const int k0 = kt * BK;
        #pragma unroll
        for (int i = 0; i < 8; i++) {
            int idx = tid + i * 128;
            int row = idx >> 3;
            int ch  = idx & 7;
            uint32_t so = SWZ_OFF(row, ch);
            cp_async16(sb + OFF_A + so, A + (size_t)row * DIM + k0 + ch * 8);
        }
        #pragma unroll
        for (int i = 0; i < 4; i++) {
            int idx = tid + i * 128;
            int row = idx >> 3;
            int ch  = idx & 7;
            uint32_t so = SWZ_OFF(row, ch);
            cp_async16(sb + OFF_B + so, B + (size_t)row * DIM + k0 + ch * 8);
        }
        asm volatile("cp.async.commit_group;" ::: "memory");
    };

    float acc[4][4][4];
    #pragma unroll
    for (int i = 0; i < 4; i++)
        #pragma unroll
        for (int j = 0; j < 4; j++)
            #pragma unroll
            for (int k = 0; k < 4; k++) acc[i][j][k] = 0.0f;

    load_stage(0, 0);
    load_stage(1, 1);

    // ldmatrix row/chunk mapping
    const int arow = wm * 64 + (lane & 15);   // + mi*16
    const int brow = wn * 32 + (lane & 15);   // + nj*16
    const int chi  = lane >> 4;               // 0 or 1

    uint32_t a[2][4][4], b[2][2][4];

    for (int kt = 0; kt < NKT; kt++) {
        if (kt + 1 < NKT)
            asm volatile("cp.async.wait_group 1;" ::: "memory");
        else
            asm volatile("cp.async.wait_group 0;" ::: "memory");
        __syncthreads();

        if (kt + 2 < NKT) load_stage((kt + 2) % NSTG, kt + 2);

        const uint32_t sb = sbase + (kt % NSTG) * STAGE;
        const uint32_t sA = sb + OFF_A;
        const uint32_t sB = sb + OFF_B;

        auto ld_frags = [&](int ks, uint32_t af[4][4], uint32_t bf[2][4]) {
            const int ch = ks * 2 + chi;
            #pragma unroll
            for (int mi = 0; mi < 4; mi++) {
                uint32_t ro = SWZ_OFF(arow + mi * 16, ch);
                ldsm_x4(af[mi][0], af[mi][1], af[mi][2], af[mi][3], sA + ro);
            }
            #pragma unroll
            for (int nj = 0; nj < 2; nj++) {
                uint32_t ro = SWZ_OFF(brow + nj * 16, ch);
                ldsm_x4(bf[nj][0], bf[nj][1], bf[nj][2], bf[nj][3], sB + ro);
            }
        };

        ld_frags(0, a[0], b[0]);

        #pragma unroll
        for (int ks = 0; ks < 4; ks++) {
            const int cur = ks & 1;
            const int nxt = cur ^ 1;
            if (ks < 3) ld_frags(ks + 1, a[nxt], b[nxt]);

            #pragma unroll
            for (int mi = 0; mi < 4; mi++) {
                #pragma unroll
                for (int nt = 0; nt < 4; nt++) {
                    const int nj = nt >> 1, h = nt & 1;
                    mma16816(acc[mi][nt], a[cur][mi], b[cur][nj][h], b[cur][nj][h + 2]);
                }
            }
        }
    }

    // epilogue: scale by 20, direct float2 stores
    const int erow = by * BM + wm * 64 + (lane >> 2);
    const int ecol = bx * BN + wn * 32 + (lane & 3) * 2;
    #pragma unroll
    for (int mi = 0; mi < 4; mi++) {
        #pragma unroll
        for (int nt = 0; nt < 4; nt++) {
            float* p0 = C + (size_t)(erow + mi * 16) * NROWS + ecol + nt * 8;
            float* p1 = p0 + 8 * NROWS;
            *(float2*)p0 = make_float2(acc[mi][nt][0] * TEMP_INV,
                                       acc[mi][nt][1] * TEMP_INV);
            *(float2*)p1 = make_float2(acc[mi][nt][2] * TEMP_INV,
                                       acc[mi][nt][3] * TEMP_INV);
        }
    }
}

extern "C" void kernel_launch(void* const* d_in, const int* in_sizes, int n_in,
                              void* d_out, int out_size) {
    const float* x = (const float*)d_in[0];
    const float* y = (const float*)d_in[1];
    float* out = (float*)d_out;

    normalize_kernel<<<2 * NROWS, 256>>>(x, y);

    cudaFuncSetAttribute(gemm_hmma,
                         cudaFuncAttributeMaxDynamicSharedMemorySize, SMEM_TOTAL);
    dim3 grid(NROWS / BN, NROWS / BM);
    gemm_hmma<<<grid, 128, SMEM_TOTAL>>>(out);
}

// round 10
// speedup vs baseline: 1.1425x; 1.0438x over previous
#include <cuda_runtime.h>
#include <cuda_fp16.h>
#include <cstdint>
#include <math.h>

#define NROWS 4096
#define DIM   1024
#define TEMP_INV 20.0f
#define EPS 1e-8f

#define BM 128
#define BN 128
#define BK 64
#define NKT (DIM / BK)        // 16 k-tiles
#define ROWB 128              // smem row stride in bytes (XOR swizzle, 8 chunks)
#define MAT_BYTES (128 * ROWB)        // 16384 per matrix per stage
#define OFF_A 0
#define OFF_B MAT_BYTES
#define STAGE  (2 * MAT_BYTES)        // 32768
#define NSTG   3
#define SMEM_TOTAL (NSTG * STAGE)     // 98304 -> 2 CTAs/SM

// swizzled byte offset: row r (0..127), 16B chunk c (0..7); conflict-free for
// 8-row ldmatrix phases and the cp.async write pattern
#define SWZ_OFF(r, c) ((r) * ROWB + ((((c) ^ ((r) & 7))) << 4))

// fp16 normalized inputs (allocation-free scratch)
__device__ __half g_xh[NROWS * DIM];
__device__ __half g_yh[NROWS * DIM];

// ---------------------------------------------------------------------------
// helpers
// ---------------------------------------------------------------------------
__device__ __forceinline__ uint32_t smem_to_u32(const void* p) {
    uint32_t a;
    asm("{ .reg .u64 t; cvta.to.shared.u64 t, %1; cvt.u32.u64 %0, t; }"
        : "=r"(a) : "l"(p));
    return a;
}

__device__ __forceinline__ void cp_async16(uint32_t s, const void* g) {
    asm volatile("cp.async.cg.shared.global [%0], [%1], 16;" :: "r"(s), "l"(g));
}

__device__ __forceinline__ void ldsm_x4(uint32_t& r0, uint32_t& r1,
                                        uint32_t& r2, uint32_t& r3, uint32_t addr) {
    asm volatile("ldmatrix.sync.aligned.m8n8.x4.shared.b16 {%0,%1,%2,%3}, [%4];"
                 : "=r"(r0), "=r"(r1), "=r"(r2), "=r"(r3) : "r"(addr));
}

__device__ __forceinline__ void mma16816(float* d, const uint32_t* a,
                                         uint32_t b0, uint32_t b1) {
    asm volatile(
        "mma.sync.aligned.m16n8k16.row.col.f32.f16.f16.f32 "
        "{%0,%1,%2,%3}, {%4,%5,%6,%7}, {%8,%9}, {%0,%1,%2,%3};"
        : "+f"(d[0]), "+f"(d[1]), "+f"(d[2]), "+f"(d[3])
        : "r"(a[0]), "r"(a[1]), "r"(a[2]), "r"(a[3]), "r"(b0), "r"(b1));
}

// ---------------------------------------------------------------------------
// Kernel 1: normalize rows, emit fp16. One warp per row, no block sync.
// ---------------------------------------------------------------------------
__global__ __launch_bounds__(256) void normalize_kernel(
    const float* __restrict__ x, const float* __restrict__ y) {
    const int lane = threadIdx.x & 31;
    const int row = blockIdx.x * 8 + (threadIdx.x >> 5);

    const float* src;
    __half* dst;
    if (row < NROWS) {
        src = x + (size_t)row * DIM;
        dst = g_xh + (size_t)row * DIM;
    } else {
        src = y + (size_t)(row - NROWS) * DIM;
        dst = g_yh + (size_t)(row - NROWS) * DIM;
    }

    float4 v[8];
    float s = 0.0f;
    #pragma unroll
    for (int i = 0; i < 8; i++) {
        v[i] = ((const float4*)src)[lane + i * 32];
        s += v[i].x * v[i].x + v[i].y * v[i].y + v[i].z * v[i].z + v[i].w * v[i].w;
    }
    #pragma unroll
    for (int o = 16; o; o >>= 1) s += __shfl_xor_sync(0xffffffffu, s, o);
    float inv = 1.0f / fmaxf(sqrtf(s), EPS);

    #pragma unroll
    for (int i = 0; i < 8; i++) {
        __half2 p0 = __floats2half2_rn(v[i].x * inv, v[i].y * inv);
        __half2 p1 = __floats2half2_rn(v[i].z * inv, v[i].w * inv);
        ((uint2*)dst)[lane + i * 32] = make_uint2(*(uint32_t*)&p0, *(uint32_t*)&p1);
    }
}

// ---------------------------------------------------------------------------
// Kernel 2: fp16 HMMA GEMM. C[n][m] = 20 * (xn[n] . yn[m])
// 128x128 CTA tile, BK=64, 3-stage cp.async pipeline with split-issue loads,
// 4 warps (2x2), warp tile 64x64, register double-buffered frags, 2 CTAs/SM.
// ---------------------------------------------------------------------------
__global__ __launch_bounds__(128, 2) void gemm_hmma(float* __restrict__ C) {
    extern __shared__ __align__(128) char smem[];
    const int tid = threadIdx.x;
    const int lane = tid & 31;
    const int wid = tid >> 5;
    const int wm = wid >> 1;       // 0..1  (M)
    const int wn = wid & 1;        // 0..1  (N)
    const int bx = blockIdx.x;     // N tile
    const int by = blockIdx.y;     // M tile

    const uint32_t sbase = smem_to_u32(smem);

    const __half* __restrict__ A = g_xh + (size_t)(by * BM) * DIM;
    const __half* __restrict__ B = g_yh + (size_t)(bx * BN) * DIM;

    // loader halves: 128 rows x 8 chunks per matrix; 8/thread/matrix total,
    // issued as two halves of 4+4 to spread LSU dispatch pressure.
    auto load_half = [&](int sidx, int kt, int half) {
        const uint32_t sb = sbase + sidx * STAGE;
        const int k0 = kt * BK;
        #pragma unroll
        for (int i = half * 4; i < half * 4 + 4; i++) {
            int idx = tid + i * 128;
            int row = idx >> 3;
            int ch  = idx & 7;
            uint32_t so = SWZ_OFF(row, ch);
            size_t go = (size_t)row * DIM + k0 + ch * 8;
            cp_async16(sb + OFF_A + so, A + go);
            cp_async16(sb + OFF_B + so, B + go);
        }
    };
    auto commit = [] {
        asm volatile("cp.async.commit_group;" ::: "memory");
    };

    float acc[4][8][4];
    #pragma unroll
    for (int i = 0; i < 4; i++)
        #pragma unroll
        for (int j = 0; j < 8; j++)
            #pragma unroll
            for (int k = 0; k < 4; k++) acc[i][j][k] = 0.0f;

    load_half(0, 0, 0); load_half(0, 0, 1); commit();
    load_half(1, 1, 0); load_half(1, 1, 1); commit();

    // ldmatrix row/chunk mapping
    const int arow = wm * 64 + (lane & 15);   // + mi*16
    const int brow = wn * 64 + (lane & 15);   // + nj*16
    const int chi  = lane >> 4;               // 0 or 1

    uint32_t a[2][4][4], b[2][4][4];

    for (int kt = 0; kt < NKT; kt++) {
        if (kt + 1 < NKT)
            asm volatile("cp.async.wait_group 1;" ::: "memory");
        else
            asm volatile("cp.async.wait_group 0;" ::: "memory");
        __syncthreads();

        const uint32_t sb = sbase + (kt % NSTG) * STAGE;
        const uint32_t sA = sb + OFF_A;
        const uint32_t sB = sb + OFF_B;
        const bool pf = (kt + 2 < NKT);
        const int pidx = (kt + 2) % NSTG;

        auto ld_frags = [&](int ks, uint32_t af[4][4], uint32_t bf[4][4]) {
            const int ch = ks * 2 + chi;
            #pragma unroll
            for (int mi = 0; mi < 4; mi++) {
                uint32_t ro = SWZ_OFF(arow + mi * 16, ch);
                ldsm_x4(af[mi][0], af[mi][1], af[mi][2], af[mi][3], sA + ro);
            }
            #pragma unroll
            for (int nj = 0; nj < 4; nj++) {
                uint32_t ro = SWZ_OFF(brow + nj * 16, ch);
                ldsm_x4(bf[nj][0], bf[nj][1], bf[nj][2], bf[nj][3], sB + ro);
            }
        };
        auto mma_block = [&](uint32_t af[4][4], uint32_t bf[4][4]) {
            #pragma unroll
            for (int mi = 0; mi < 4; mi++) {
                #pragma unroll
                for (int nt = 0; nt < 8; nt++) {
                    const int nj = nt >> 1, h = nt & 1;
                    mma16816(acc[mi][nt], af[mi], bf[nj][h], bf[nj][h + 2]);
                }
            }
        };

        ld_frags(0, a[0], b[0]);

        // ks = 0
        ld_frags(1, a[1], b[1]);
        mma_block(a[0], b[0]);
        if (pf) load_half(pidx, kt + 2, 0);     // spread LSU pressure

        // ks = 1
        ld_frags(2, a[0], b[0]);
        mma_block(a[1], b[1]);
        if (pf) { load_half(pidx, kt + 2, 1); }
        commit();                                // one group per stage (empty if !pf)

        // ks = 2
        ld_frags(3, a[1], b[1]);
        mma_block(a[0], b[0]);

        // ks = 3
        mma_block(a[1], b[1]);
    }

    // epilogue: scale by 20, direct float2 stores
    const int erow = by * BM + wm * 64 + (lane >> 2);
    const int ecol = bx * BN + wn * 64 + (lane & 3) * 2;
    #pragma unroll
    for (int mi = 0; mi < 4; mi++) {
        #pragma unroll
        for (int nt = 0; nt < 8; nt++) {
            float* p0 = C + (size_t)(erow + mi * 16) * NROWS + ecol + nt * 8;
            float* p1 = p0 + 8 * NROWS;
            *(float2*)p0 = make_float2(acc[mi][nt][0] * TEMP_INV,
                                       acc[mi][nt][1] * TEMP_INV);
            *(float2*)p1 = make_float2(acc[mi][nt][2] * TEMP_INV,
                                       acc[mi][nt][3] * TEMP_INV);
        }
    }
}

extern "C" void kernel_launch(void* const* d_in, const int* in_sizes, int n_in,
                              void* d_out, int out_size) {
    const float* x = (const float*)d_in[0];
    const float* y = (const float*)d_in[1];
    float* out = (float*)d_out;

    normalize_kernel<<<2 * NROWS / 8, 256>>>(x, y);

    cudaFuncSetAttribute(gemm_hmma,
                         cudaFuncAttributeMaxDynamicSharedMemorySize, SMEM_TOTAL);
    dim3 grid(NROWS / BN, NROWS / BM);
    gemm_hmma<<<grid, 128, SMEM_TOTAL>>>(out);
}